// round 1
// baseline (speedup 1.0000x reference)
#include <cuda_runtime.h>
#include <math.h>

#define Bc   16
#define Mc   256
#define Nc   512
#define H1c  16
#define H2c  8
#define Uc   8
#define OUTc 4
#define BNc  (Bc*Nc)

// ---- scratch (static device globals; no allocation) ----
__device__ float g_G[(size_t)Bc*Nc*Nc];   // 16 MB Gram
__device__ float g_u[BNc*Uc];
__device__ float g_g[BNc*H1c];
__device__ float g_a[BNc*H1c];            // a_i = W1_un u_i + b1 + w1s*sigma2
__device__ float g_c[BNc*H1c];            // c_j = W1_uj u_j
__device__ float g_h2s[BNc*H2c];          // sum_j relu(h2)

// ============================================================
// K1: G = A^T A per batch, symmetric upper-triangular tiles.
// 64x64 tile, 256 threads, 4x4 micro-tile, K-chunk 16.
// ============================================================
__global__ void __launch_bounds__(256) gram_kernel(const float* __restrict__ A) {
    int b = blockIdx.y;
    int idx = blockIdx.x;                 // 0..35 -> (ti<=tj) of 8x8 tiles
    int ti = 0;
    while (idx >= 8 - ti) { idx -= 8 - ti; ti++; }
    int tj = ti + idx;

    const float* Ab = A + (size_t)b * Mc * Nc;
    __shared__ float sA[16][68];
    __shared__ float sB[16][68];

    int tid = threadIdx.x;
    int tx = tid & 15, ty = tid >> 4;
    int i0 = ti * 64, j0 = tj * 64;
    int lr = ty, lc = tx * 4;             // load: row lr (0..15), col lc (0..60)

    float acc[4][4];
#pragma unroll
    for (int r_ = 0; r_ < 4; r_++)
#pragma unroll
        for (int s_ = 0; s_ < 4; s_++) acc[r_][s_] = 0.f;

    for (int k0 = 0; k0 < Mc; k0 += 16) {
        float4 av = *(const float4*)(Ab + (size_t)(k0 + lr) * Nc + i0 + lc);
        float4 bv = *(const float4*)(Ab + (size_t)(k0 + lr) * Nc + j0 + lc);
        __syncthreads();
        *(float4*)&sA[lr][lc] = av;
        *(float4*)&sB[lr][lc] = bv;
        __syncthreads();
#pragma unroll
        for (int k = 0; k < 16; k++) {
            float4 a4 = *(const float4*)&sA[k][ty * 4];
            float4 b4 = *(const float4*)&sB[k][tx * 4];
            float ar[4] = {a4.x, a4.y, a4.z, a4.w};
            float br[4] = {b4.x, b4.y, b4.z, b4.w};
#pragma unroll
            for (int r_ = 0; r_ < 4; r_++)
#pragma unroll
                for (int s_ = 0; s_ < 4; s_++)
                    acc[r_][s_] = fmaf(ar[r_], br[s_], acc[r_][s_]);
        }
    }

    float* Gb = g_G + (size_t)b * Nc * Nc;
#pragma unroll
    for (int r_ = 0; r_ < 4; r_++) {
        float4 v = make_float4(acc[r_][0], acc[r_][1], acc[r_][2], acc[r_][3]);
        *(float4*)(Gb + (size_t)(i0 + ty * 4 + r_) * Nc + j0 + tx * 4) = v;
    }
    if (ti != tj) {                       // mirror into lower triangle
#pragma unroll
        for (int s_ = 0; s_ < 4; s_++) {
            float4 v = make_float4(acc[0][s_], acc[1][s_], acc[2][s_], acc[3][s_]);
            *(float4*)(Gb + (size_t)(j0 + tx * 4 + s_) * Nc + i0 + ty * 4) = v;
        }
    }
}

// ============================================================
// K2: ATy, diag(G), u0 = W_init feat + b; zero g; compute a,c.
// grid (N/128, B), block 128.
// ============================================================
__global__ void init_kernel(const float* __restrict__ A, const float* __restrict__ y,
                            const float* __restrict__ sigma2,
                            const float* __restrict__ w_init, const float* __restrict__ b_init,
                            const float* __restrict__ w_p1, const float* __restrict__ b_p1) {
    int b = blockIdx.y;
    int n = blockIdx.x * 128 + threadIdx.x;
    __shared__ float sy[Mc];
    for (int m = threadIdx.x; m < Mc; m += 128) sy[m] = y[b * Mc + m];
    __syncthreads();

    const float* Ab = A + (size_t)b * Mc * Nc + n;
    float aty = 0.f;
    for (int m = 0; m < Mc; m++) aty = fmaf(Ab[(size_t)m * Nc], sy[m], aty);

    float diag = g_G[(size_t)b * Nc * Nc + (size_t)n * Nc + n];
    float sig = sigma2[b];
    int node = b * Nc + n;

    float u[Uc];
#pragma unroll
    for (int o = 0; o < Uc; o++) {
        u[o] = b_init[o] + w_init[o * 3 + 0] * aty + w_init[o * 3 + 1] * diag
             + w_init[o * 3 + 2] * sig;
        g_u[node * Uc + o] = u[o];
    }
#pragma unroll
    for (int k = 0; k < H1c; k++) g_g[node * H1c + k] = 0.f;

#pragma unroll
    for (int o = 0; o < H1c; o++) {
        float av = b_p1[o] + w_p1[o * 18 + 17] * sig;
        float cv = 0.f;
#pragma unroll
        for (int k = 0; k < Uc; k++) {
            av = fmaf(w_p1[o * 18 + k], u[k], av);
            cv = fmaf(w_p1[o * 18 + 8 + k], u[k], cv);
        }
        g_a[node * H1c + o] = av;
        g_c[node * H1c + o] = cv;
    }
}

// ============================================================
// K4: the pair kernel. Block = 16 i's x 16 j-lanes (256 thr).
// Per pair: h1 = relu(a_i + c_j + w1g*G); acc += relu(W2 h1 + b2) (off-diag).
// W2 kept in registers; c_j tiles staged in smem [128][20].
// ============================================================
__global__ void __launch_bounds__(256, 1)
pair_kernel(const float* __restrict__ w_p1, const float* __restrict__ w_p2,
            const float* __restrict__ b_p2) {
    int b = blockIdx.y;
    int i0 = blockIdx.x * 16;
    int tid = threadIdx.x;
    int iy = tid >> 4, jx = tid & 15;
    int i = i0 + iy;
    int nodei = b * Nc + i;

    __shared__ float cS[128][20];

    float areg[16], w1g[16], W2[8][16], b2r[8];
#pragma unroll
    for (int k = 0; k < 16; k++) areg[k] = g_a[nodei * 16 + k];
#pragma unroll
    for (int k = 0; k < 16; k++) w1g[k] = __ldg(&w_p1[k * 18 + 16]);
#pragma unroll
    for (int o = 0; o < 8; o++) {
        b2r[o] = __ldg(&b_p2[o]);
#pragma unroll
        for (int k = 0; k < 16; k++) W2[o][k] = __ldg(&w_p2[o * 16 + k]);
    }
    float acc[8] = {0.f, 0.f, 0.f, 0.f, 0.f, 0.f, 0.f, 0.f};

    const float* Grow = g_G + (size_t)b * Nc * Nc + (size_t)i * Nc;
    const float* cbase = g_c + (size_t)(b * Nc) * 16;

    for (int jc = 0; jc < Nc; jc += 128) {
        __syncthreads();
        const float4* src = (const float4*)(cbase + (size_t)jc * 16);
        {
            float4 v0 = src[tid];
            float4 v1 = src[tid + 256];
            int jj0 = tid >> 2, k40 = (tid & 3) << 2;
            int jj1 = (tid + 256) >> 2;
            *(float4*)&cS[jj0][k40] = v0;
            *(float4*)&cS[jj1][k40] = v1;
        }
        __syncthreads();
#pragma unroll
        for (int s = 0; s < 8; s++) {
            int jj = jx + s * 16;
            int j = jc + jj;
            float Gv = Grow[j];
            float4 c0 = *(const float4*)&cS[jj][0];
            float4 c1 = *(const float4*)&cS[jj][4];
            float4 c2 = *(const float4*)&cS[jj][8];
            float4 c3 = *(const float4*)&cS[jj][12];
            float cv[16] = {c0.x, c0.y, c0.z, c0.w, c1.x, c1.y, c1.z, c1.w,
                            c2.x, c2.y, c2.z, c2.w, c3.x, c3.y, c3.z, c3.w};
            float h1[16];
#pragma unroll
            for (int k = 0; k < 16; k++)
                h1[k] = fmaxf(fmaf(w1g[k], Gv, areg[k]) + cv[k], 0.f);
            float mask = (j == i) ? 0.f : 1.f;
#pragma unroll
            for (int o = 0; o < 8; o++) {
                float t2 = b2r[o];
#pragma unroll
                for (int k = 0; k < 16; k++) t2 = fmaf(W2[o][k], h1[k], t2);
                acc[o] = fmaf(mask, fmaxf(t2, 0.f), acc[o]);
            }
        }
    }

    // reduce the 8-dim accumulator across the 16 j-lanes of this i
#pragma unroll
    for (int o = 0; o < 8; o++) {
#pragma unroll
        for (int off = 8; off; off >>= 1)
            acc[o] += __shfl_down_sync(0xffffffffu, acc[o], off, 16);
    }
    if (jx == 0) {
#pragma unroll
        for (int o = 0; o < 8; o++) g_h2s[nodei * 8 + o] = acc[o];
    }
}

// ============================================================
// K5: per-node m_sum = W3*h2sum + (N-1)b3, GRU update, u = W_up g + b;
// also recompute a,c for next layer. block 128, weights in smem.
// ============================================================
__global__ void gru_kernel(const float* __restrict__ w_p3, const float* __restrict__ b_p3,
                           const float* __restrict__ w_ih, const float* __restrict__ b_ih,
                           const float* __restrict__ w_hh, const float* __restrict__ b_hh,
                           const float* __restrict__ w_up, const float* __restrict__ b_up,
                           const float* __restrict__ w_p1, const float* __restrict__ b_p1,
                           const float* __restrict__ r, const float* __restrict__ Sigma,
                           const float* __restrict__ sigma2) {
    __shared__ float s_wp3[64], s_bp3[8], s_wih[480], s_bih[48], s_whh[768], s_bhh[48],
                     s_wup[128], s_bup[8], s_wp1[288], s_bp1[16];
    int tid = threadIdx.x;
    for (int t = tid; t < 64;  t += 128) s_wp3[t] = w_p3[t];
    for (int t = tid; t < 480; t += 128) s_wih[t] = w_ih[t];
    for (int t = tid; t < 768; t += 128) s_whh[t] = w_hh[t];
    for (int t = tid; t < 288; t += 128) s_wp1[t] = w_p1[t];
    if (tid < 128) s_wup[tid] = w_up[tid];
    if (tid < 48) { s_bih[tid] = b_ih[tid]; s_bhh[tid] = b_hh[tid]; }
    if (tid < 16) s_bp1[tid] = b_p1[tid];
    if (tid < 8)  { s_bp3[tid] = b_p3[tid]; s_bup[tid] = b_up[tid]; }
    __syncthreads();

    int node = blockIdx.x * 128 + tid;
    int b = node / Nc;

    float h2s[8];
#pragma unroll
    for (int q = 0; q < 8; q++) h2s[q] = g_h2s[node * 8 + q];

    float gin[10];
#pragma unroll
    for (int o = 0; o < 8; o++) {
        float m = s_bp3[o] * (float)(Nc - 1);
#pragma unroll
        for (int q = 0; q < 8; q++) m = fmaf(s_wp3[o * 8 + q], h2s[q], m);
        gin[o] = m;
    }
    gin[8] = r[node];
    gin[9] = Sigma[node];

    float g[16];
#pragma unroll
    for (int k = 0; k < 16; k++) g[k] = g_g[node * 16 + k];

    float gi[48], gh[48];
#pragma unroll
    for (int t = 0; t < 48; t++) {
        float a = s_bih[t];
#pragma unroll
        for (int k = 0; k < 10; k++) a = fmaf(s_wih[t * 10 + k], gin[k], a);
        gi[t] = a;
        float hsum = s_bhh[t];
#pragma unroll
        for (int k = 0; k < 16; k++) hsum = fmaf(s_whh[t * 16 + k], g[k], hsum);
        gh[t] = hsum;
    }

    float gn[16];
#pragma unroll
    for (int t = 0; t < 16; t++) {
        float rr = 1.f / (1.f + expf(-(gi[t] + gh[t])));
        float zz = 1.f / (1.f + expf(-(gi[16 + t] + gh[16 + t])));
        float nn = tanhf(gi[32 + t] + rr * gh[32 + t]);
        gn[t] = (1.f - zz) * nn + zz * g[t];
        g_g[node * 16 + t] = gn[t];
    }

    float u[8];
#pragma unroll
    for (int o = 0; o < 8; o++) {
        float uv = s_bup[o];
#pragma unroll
        for (int k = 0; k < 16; k++) uv = fmaf(s_wup[o * 16 + k], gn[k], uv);
        u[o] = uv;
        g_u[node * 8 + o] = uv;
    }

    float sig = sigma2[b];
#pragma unroll
    for (int o = 0; o < 16; o++) {
        float av = s_bp1[o] + s_wp1[o * 18 + 17] * sig;
        float cv = 0.f;
#pragma unroll
        for (int k = 0; k < 8; k++) {
            av = fmaf(s_wp1[o * 18 + k], u[k], av);
            cv = fmaf(s_wp1[o * 18 + 8 + k], u[k], cv);
        }
        g_a[node * 16 + o] = av;
        g_c[node * 16 + o] = cv;
    }
}

// ============================================================
// K6: readout MLP + softmax, and emit (probs, u, g) into d_out.
// ============================================================
__global__ void readout_kernel(const float* __restrict__ w_r1, const float* __restrict__ b_r1,
                               const float* __restrict__ w_r2, const float* __restrict__ b_r2,
                               const float* __restrict__ w_r3, const float* __restrict__ b_r3,
                               float* __restrict__ out) {
    __shared__ float s_w1[128], s_b1[16], s_w2[128], s_b2[8], s_w3[32], s_b3[4];
    int tid = threadIdx.x;
    if (tid < 128) { s_w1[tid] = w_r1[tid]; s_w2[tid] = w_r2[tid]; }
    if (tid < 32) s_w3[tid] = w_r3[tid];
    if (tid < 16) s_b1[tid] = b_r1[tid];
    if (tid < 8)  s_b2[tid] = b_r2[tid];
    if (tid < 4)  s_b3[tid] = b_r3[tid];
    __syncthreads();

    int node = blockIdx.x * 128 + tid;

    float u[8];
#pragma unroll
    for (int o = 0; o < 8; o++) u[o] = g_u[node * 8 + o];

    float h1[16];
#pragma unroll
    for (int t = 0; t < 16; t++) {
        float a = s_b1[t];
#pragma unroll
        for (int k = 0; k < 8; k++) a = fmaf(s_w1[t * 8 + k], u[k], a);
        h1[t] = fmaxf(a, 0.f);
    }
    float h2[8];
#pragma unroll
    for (int t = 0; t < 8; t++) {
        float a = s_b2[t];
#pragma unroll
        for (int k = 0; k < 16; k++) a = fmaf(s_w2[t * 16 + k], h1[k], a);
        h2[t] = fmaxf(a, 0.f);
    }
    float lg[4];
#pragma unroll
    for (int t = 0; t < 4; t++) {
        float a = s_b3[t];
#pragma unroll
        for (int k = 0; k < 8; k++) a = fmaf(s_w3[t * 8 + k], h2[k], a);
        lg[t] = a;
    }
    float mx = fmaxf(fmaxf(lg[0], lg[1]), fmaxf(lg[2], lg[3]));
    float e0 = expf(lg[0] - mx), e1 = expf(lg[1] - mx),
          e2 = expf(lg[2] - mx), e3 = expf(lg[3] - mx);
    float inv = 1.f / (e0 + e1 + e2 + e3);

    // output layout: probs [B,N,4] | u [B,N,8] | g [B*N,16]
    out[node * 4 + 0] = e0 * inv;
    out[node * 4 + 1] = e1 * inv;
    out[node * 4 + 2] = e2 * inv;
    out[node * 4 + 3] = e3 * inv;
#pragma unroll
    for (int o = 0; o < 8; o++) out[BNc * 4 + node * 8 + o] = u[o];
#pragma unroll
    for (int k = 0; k < 16; k++) out[BNc * 12 + node * 16 + k] = g_g[node * 16 + k];
}

// ============================================================
extern "C" void kernel_launch(void* const* d_in, const int* in_sizes, int n_in,
                              void* d_out, int out_size) {
    const float* y      = (const float*)d_in[0];
    const float* A      = (const float*)d_in[1];
    const float* sigma2 = (const float*)d_in[2];
    const float* r      = (const float*)d_in[3];
    const float* Sigma  = (const float*)d_in[4];
    const float* w_init = (const float*)d_in[5];
    const float* b_init = (const float*)d_in[6];
    const float* w_p1   = (const float*)d_in[7];
    const float* b_p1   = (const float*)d_in[8];
    const float* w_p2   = (const float*)d_in[9];
    const float* b_p2   = (const float*)d_in[10];
    const float* w_p3   = (const float*)d_in[11];
    const float* b_p3   = (const float*)d_in[12];
    const float* w_ih   = (const float*)d_in[13];
    const float* b_ih   = (const float*)d_in[14];
    const float* w_hh   = (const float*)d_in[15];
    const float* b_hh   = (const float*)d_in[16];
    const float* w_up   = (const float*)d_in[17];
    const float* b_up   = (const float*)d_in[18];
    const float* w_r1   = (const float*)d_in[19];
    const float* b_r1   = (const float*)d_in[20];
    const float* w_r2   = (const float*)d_in[21];
    const float* b_r2   = (const float*)d_in[22];
    const float* w_r3   = (const float*)d_in[23];
    const float* b_r3   = (const float*)d_in[24];

    gram_kernel<<<dim3(36, Bc), 256>>>(A);
    init_kernel<<<dim3(Nc / 128, Bc), 128>>>(A, y, sigma2, w_init, b_init, w_p1, b_p1);
    for (int l = 0; l < 2; l++) {
        pair_kernel<<<dim3(Nc / 16, Bc), 256>>>(w_p1, w_p2, b_p2);
        gru_kernel<<<BNc / 128, 128>>>(w_p3, b_p3, w_ih, b_ih, w_hh, b_hh,
                                       w_up, b_up, w_p1, b_p1, r, Sigma, sigma2);
    }
    readout_kernel<<<BNc / 128, 128>>>(w_r1, b_r1, w_r2, b_r2, w_r3, b_r3,
                                       (float*)d_out);
}